// round 5
// baseline (speedup 1.0000x reference)
#include <cuda_runtime.h>
#include <cuda_bf16.h>
#include <math.h>
#include <stdint.h>

#define C_CLASSES 512
#define DDIM      1024
#define EPS_F     1e-30f
#define SCALE_F   50.0f
#define MAX_N     65536
#define QMAX      16256.0f   // 127*128 + 64 headroom -> |q| <= 16256

// ---------------- scratch (device globals; no allocations allowed) ----------------
__device__ float    g_sums[C_CLASSES * DDIM];
__device__ uint32_t g_qah[(size_t)MAX_N * 256];    // A hi int8, packed 4/word, [row][256]
__device__ uint32_t g_qal[(size_t)MAX_N * 256];    // A lo int8
__device__ uint32_t g_qbh[C_CLASSES * 256];        // B hi int8 (pre-scaled means)
__device__ uint32_t g_qbl[C_CLASSES * 256];        // B lo int8
__device__ float    g_saf[MAX_N];                  // s_a * (1/max(||t||,eps))
__device__ float    g_sbf[C_CLASSES];              // s_b
__device__ int      g_counts_i[C_CLASSES];
__device__ int      g_cursor[C_CLASSES];
__device__ int      g_offsets[C_CLASSES + 1];
__device__ int      g_idx[MAX_N];

// ---------------- PTX helpers (sm_80+ baseline features only) ----------------
__device__ __forceinline__ uint32_t smem_u32(const void* p) {
    uint32_t a;
    asm("{ .reg .u64 t; cvta.to.shared.u64 t, %1; cvt.u32.u64 %0, t; }" : "=r"(a) : "l"(p));
    return a;
}
#define CP_ASYNC16(dst, src) \
    asm volatile("cp.async.cg.shared.global [%0], [%1], 16;" :: "r"((uint32_t)(dst)), "l"(src))
#define CP_COMMIT() asm volatile("cp.async.commit_group;" ::: "memory")
#define CP_WAIT(n)  asm volatile("cp.async.wait_group %0;" :: "n"(n) : "memory")

__device__ __forceinline__ void ldsm_x4(uint32_t* r, uint32_t addr) {
    asm volatile("ldmatrix.sync.aligned.m8n8.x4.shared.b16 {%0,%1,%2,%3}, [%4];"
                 : "=r"(r[0]), "=r"(r[1]), "=r"(r[2]), "=r"(r[3]) : "r"(addr));
}
__device__ __forceinline__ void imma16832(int* c, const uint32_t* a, const uint32_t* b) {
    asm volatile("mma.sync.aligned.m16n8k32.row.col.s32.s8.s8.s32 "
                 "{%0,%1,%2,%3}, {%4,%5,%6,%7}, {%8,%9}, {%0,%1,%2,%3};"
                 : "+r"(c[0]), "+r"(c[1]), "+r"(c[2]), "+r"(c[3])
                 : "r"(a[0]), "r"(a[1]), "r"(a[2]), "r"(a[3]), "r"(b[0]), "r"(b[1]));
}
// 128B-row XOR swizzle: 16B column index c ^= (row & 7)
#define SWZ(o) ((o) ^ (((o) >> 3) & 0x70))

// quantize one float -> (qh, ql) int8 pair given inv scale
__device__ __forceinline__ void quant1(float v, float inv, int& qh, int& ql) {
    int q = __float2int_rn(v * inv);
    qh = (q + 64) >> 7;
    ql = q - (qh << 7);
}
__device__ __forceinline__ uint32_t pack4(int a, int b, int c, int d) {
    return (uint32_t)(a & 255) | ((uint32_t)(b & 255) << 8) |
           ((uint32_t)(c & 255) << 16) | ((uint32_t)(d & 255) << 24);
}

// ---------------- zero counts ----------------
__global__ void zero_kernel() {
    int i = threadIdx.x;
    if (i < C_CLASSES) g_counts_i[i] = 0;
}

// ---------------- histogram of labels ----------------
__global__ void count_kernel(const int* __restrict__ labels, int n) {
    __shared__ int hist[C_CLASSES];
    for (int i = threadIdx.x; i < C_CLASSES; i += blockDim.x) hist[i] = 0;
    __syncthreads();
    for (int i = blockIdx.x * blockDim.x + threadIdx.x; i < n; i += gridDim.x * blockDim.x)
        atomicAdd(&hist[labels[i]], 1);
    __syncthreads();
    for (int i = threadIdx.x; i < C_CLASSES; i += blockDim.x) {
        int v = hist[i];
        if (v) atomicAdd(&g_counts_i[i], v);
    }
}

// ---------------- exclusive scan over 512 counts ----------------
__global__ void scan_kernel() {
    __shared__ int tmp[C_CLASSES];
    int t = threadIdx.x;
    int v = g_counts_i[t];
    tmp[t] = v;
    __syncthreads();
    for (int off = 1; off < C_CLASSES; off <<= 1) {
        int x = (t >= off) ? tmp[t - off] : 0;
        __syncthreads();
        tmp[t] += x;
        __syncthreads();
    }
    g_offsets[t] = tmp[t] - v;
    g_cursor[t]  = tmp[t] - v;
    if (t == C_CLASSES - 1) g_offsets[C_CLASSES] = tmp[t];
}

// ---------------- scatter row indices into class buckets ----------------
__global__ void scatter_kernel(const int* __restrict__ labels, int n) {
    int i = blockIdx.x * blockDim.x + threadIdx.x;
    if (i < n) {
        int p = atomicAdd(&g_cursor[labels[i]], 1);
        g_idx[p] = i;
    }
}

// ---------------- per-class gather + register accumulation ----------------
__global__ void classsum_kernel(const float* __restrict__ ctx) {
    const int c   = blockIdx.x;
    const int col = blockIdx.y * 256 + threadIdx.x;
    const int beg = g_offsets[c];
    const int end = g_offsets[c + 1];

    float a0 = 0.f, a1 = 0.f, a2 = 0.f, a3 = 0.f;
    int i = beg;
    for (; i + 3 < end; i += 4) {
        int r0 = g_idx[i], r1 = g_idx[i + 1], r2 = g_idx[i + 2], r3 = g_idx[i + 3];
        a0 += ctx[(size_t)r0 * DDIM + col];
        a1 += ctx[(size_t)r1 * DDIM + col];
        a2 += ctx[(size_t)r2 * DDIM + col];
        a3 += ctx[(size_t)r3 * DDIM + col];
    }
    for (; i < end; i++) a0 += ctx[(size_t)g_idx[i] * DDIM + col];
    g_sums[(size_t)c * DDIM + col] = (a0 + a1) + (a2 + a3);
}

// ---------------- finalize: means -> d_out; scaled int8 hi/lo B + s_b ----------------
// thread tid handles 4 contiguous dims [tid*4, tid*4+4)
__global__ void finalize_kernel(float* __restrict__ means_out) {
    const int c   = blockIdx.x;
    const int tid = threadIdx.x;
    const float cinv = 1.f / fmaxf((float)g_counts_i[c], 1.f);

    float4 v = *(const float4*)&g_sums[(size_t)c * DDIM + tid * 4];
    v.x *= cinv; v.y *= cinv; v.z *= cinv; v.w *= cinv;
    *(float4*)&means_out[(size_t)c * DDIM + tid * 4] = v;

    float ss = v.x * v.x + v.y * v.y + v.z * v.z + v.w * v.w;
    float am = fmaxf(fmaxf(fabsf(v.x), fabsf(v.y)), fmaxf(fabsf(v.z), fabsf(v.w)));

    __shared__ float red_s[8], red_m[8];
#pragma unroll
    for (int o = 16; o > 0; o >>= 1) {
        ss += __shfl_xor_sync(0xffffffffu, ss, o);
        am = fmaxf(am, __shfl_xor_sync(0xffffffffu, am, o));
    }
    if ((tid & 31) == 0) { red_s[tid >> 5] = ss; red_m[tid >> 5] = am; }
    __syncthreads();
    __shared__ float s_inv, s_sb;
    if (tid == 0) {
        float tot = 0.f, mx = 0.f;
#pragma unroll
        for (int k = 0; k < 8; k++) { tot += red_s[k]; mx = fmaxf(mx, red_m[k]); }
        float sc = SCALE_F / fmaxf(sqrtf(tot), EPS_F);   // scale applied to mean
        float amax = mx * sc;                            // max |scaled value|
        s_sb  = amax / QMAX;
        s_inv = (amax > 0.f) ? (QMAX / amax) * sc : 0.f; // value -> q units (incl. sc)
        g_sbf[c] = s_sb;
    }
    __syncthreads();
    const float inv = s_inv;
    int h0, l0, h1, l1, h2, l2, h3, l3;
    quant1(v.x, inv, h0, l0);
    quant1(v.y, inv, h1, l1);
    quant1(v.z, inv, h2, l2);
    quant1(v.w, inv, h3, l3);
    g_qbh[c * 256 + tid] = pack4(h0, h1, h2, h3);
    g_qbl[c * 256 + tid] = pack4(l0, l1, l2, l3);
}

// ---------------- fused: target quantization + inverse norms (one warp per row) ----------------
__global__ void quant_a_kernel(const float4* __restrict__ tgt4, int n_tgt) {
    int w    = (blockIdx.x * blockDim.x + threadIdx.x) >> 5;
    int lane = threadIdx.x & 31;
    if (w >= n_tgt) return;
    const float4* row = tgt4 + (size_t)w * (DDIM / 4);
    float4 v[8];
    float ss = 0.f, am = 0.f;
#pragma unroll
    for (int j = 0; j < 8; j++) {
        v[j] = row[lane + 32 * j];
        ss += v[j].x * v[j].x + v[j].y * v[j].y + v[j].z * v[j].z + v[j].w * v[j].w;
        am = fmaxf(am, fmaxf(fmaxf(fabsf(v[j].x), fabsf(v[j].y)),
                             fmaxf(fabsf(v[j].z), fabsf(v[j].w))));
    }
#pragma unroll
    for (int o = 16; o > 0; o >>= 1) {
        ss += __shfl_xor_sync(0xffffffffu, ss, o);
        am = fmaxf(am, __shfl_xor_sync(0xffffffffu, am, o));
    }
    float inv = (am > 0.f) ? QMAX / am : 0.f;
    if (lane == 0)
        g_saf[w] = (am / QMAX) / fmaxf(sqrtf(ss), EPS_F);
#pragma unroll
    for (int j = 0; j < 8; j++) {
        int h0, l0, h1, l1, h2, l2, h3, l3;
        quant1(v[j].x, inv, h0, l0);
        quant1(v[j].y, inv, h1, l1);
        quant1(v[j].z, inv, h2, l2);
        quant1(v[j].w, inv, h3, l3);
        int e4 = lane + 32 * j;
        g_qah[(size_t)w * 256 + e4] = pack4(h0, h1, h2, h3);
        g_qal[(size_t)w * 256 + e4] = pack4(l0, l1, l2, l3);
    }
}

// ---------------- int8x3 IMMA GEMM: out[M,512] ----------------
// CTA tile 128x128, 8 warps (4m x 2n), warp tile 32x64, K-chunk 128 int8, 3 stages.
#define MT   128
#define NT   128
#define KC   128
#define NC   (DDIM / KC)             // 8
#define OFF_AHI  0
#define OFF_ALO  16384
#define OFF_BHI  32768
#define OFF_BLO  49152
#define STAGE    65536
#define NSTAGE   3
#define SMEM_BYTES (NSTAGE * STAGE + 1024)

__device__ __forceinline__ void load_chunk(uint32_t stage, int m0, int n0, int gk0, int tid) {
    const char* Ah = (const char*)g_qah;
    const char* Al = (const char*)g_qal;
    const char* Bh = (const char*)g_qbh;
    const char* Bl = (const char*)g_qbl;
#pragma unroll
    for (int p = 0; p < 4; p++) {
        int i = tid + p * 256;
        int row = i >> 3, c16 = i & 7;
        uint32_t off = SWZ((uint32_t)row * 128 + (uint32_t)c16 * 16);
        size_t gsrc = (size_t)(m0 + row) * DDIM + gk0 + c16 * 16;
        CP_ASYNC16(stage + OFF_AHI + off, Ah + gsrc);
        CP_ASYNC16(stage + OFF_ALO + off, Al + gsrc);
    }
#pragma unroll
    for (int p = 0; p < 4; p++) {
        int i = tid + p * 256;
        int row = i >> 3, c16 = i & 7;
        uint32_t off = SWZ((uint32_t)row * 128 + (uint32_t)c16 * 16);
        size_t gsrc = (size_t)(n0 + row) * DDIM + gk0 + c16 * 16;
        CP_ASYNC16(stage + OFF_BHI + off, Bh + gsrc);
        CP_ASYNC16(stage + OFF_BLO + off, Bl + gsrc);
    }
    CP_COMMIT();
}

__global__ void __launch_bounds__(256, 1) gemm_imma_kernel(float* __restrict__ out) {
    extern __shared__ char dsm[];
    uint32_t sb = (smem_u32(dsm) + 1023) & ~1023u;

    const int tid  = threadIdx.x;
    const int wid  = tid >> 5;
    const int lane = tid & 31;
    const int wm   = wid >> 1;            // 0..3 (m)
    const int wn   = wid & 1;             // 0..1 (n)
    const int n0 = blockIdx.x * NT;
    const int m0 = blockIdx.y * MT;

    int hh[2][8][4], mx[2][8][4];
#pragma unroll
    for (int a = 0; a < 2; a++)
#pragma unroll
        for (int b = 0; b < 8; b++)
#pragma unroll
            for (int c = 0; c < 4; c++) { hh[a][b][c] = 0; mx[a][b][c] = 0; }

    // prologue: 2 chunks in flight
    load_chunk(sb + 0 * STAGE, m0, n0, 0, tid);
    load_chunk(sb + 1 * STAGE, m0, n0, KC, tid);

    // lane pieces (byte-identical to the b16 k16 ldmatrix pattern)
    const int a_r  = (lane & 15);
    const int a_kh = (lane >> 4);
    const int b_r  = (lane & 7) + ((lane >> 4) << 3);
    const int b_kh = (lane >> 3) & 1;

    int stg = 0;
    for (int c = 0; c < NC; c++) {
        if (c < NC - 1) CP_WAIT(1); else CP_WAIT(0);
        __syncthreads();
        uint32_t stage = sb + (uint32_t)stg * STAGE;

#pragma unroll
        for (int s = 0; s < 4; s++) {   // 4 k32 slices per 128B chunk
            uint32_t ah[2][4], al[2][4], bh[4][4], bl[4][4];
#pragma unroll
            for (int mt = 0; mt < 2; mt++) {
                int row = wm * 32 + mt * 16 + a_r;
                uint32_t c16 = (uint32_t)((s * 2 + a_kh) ^ (row & 7));
                uint32_t off = (uint32_t)row * 128 + c16 * 16;
                ldsm_x4(ah[mt], stage + OFF_AHI + off);
                ldsm_x4(al[mt], stage + OFF_ALO + off);
            }
#pragma unroll
            for (int nt = 0; nt < 4; nt++) {
                int row = wn * 64 + nt * 16 + b_r;
                uint32_t c16 = (uint32_t)((s * 2 + b_kh) ^ (row & 7));
                uint32_t off = (uint32_t)row * 128 + c16 * 16;
                ldsm_x4(bh[nt], stage + OFF_BHI + off);
                ldsm_x4(bl[nt], stage + OFF_BLO + off);
            }
            // pass 1: qh_a * qh_b  (16 independent IMMAs)
#pragma unroll
            for (int mt = 0; mt < 2; mt++)
#pragma unroll
                for (int nt = 0; nt < 4; nt++) {
                    imma16832(hh[mt][nt * 2 + 0], ah[mt], &bh[nt][0]);
                    imma16832(hh[mt][nt * 2 + 1], ah[mt], &bh[nt][2]);
                }
            // pass 2: qh_a * ql_b
#pragma unroll
            for (int mt = 0; mt < 2; mt++)
#pragma unroll
                for (int nt = 0; nt < 4; nt++) {
                    imma16832(mx[mt][nt * 2 + 0], ah[mt], &bl[nt][0]);
                    imma16832(mx[mt][nt * 2 + 1], ah[mt], &bl[nt][2]);
                }
            // pass 3: ql_a * qh_b
#pragma unroll
            for (int mt = 0; mt < 2; mt++)
#pragma unroll
                for (int nt = 0; nt < 4; nt++) {
                    imma16832(mx[mt][nt * 2 + 0], al[mt], &bh[nt][0]);
                    imma16832(mx[mt][nt * 2 + 1], al[mt], &bh[nt][2]);
                }
        }

        if (c + 2 < NC) {
            int nstg = stg + 2; if (nstg >= NSTAGE) nstg -= NSTAGE;
            load_chunk(sb + (uint32_t)nstg * STAGE, m0, n0, (c + 2) * KC, tid);
        }
        if (++stg == NSTAGE) stg = 0;
    }

    // epilogue: logits = (16384*hh + 128*mx) * saf[m] * sbf[n]
    const int qrow = lane >> 2;
    const int qcol = (lane & 3) * 2;
#pragma unroll
    for (int mt = 0; mt < 2; mt++) {
        int r0 = m0 + wm * 32 + mt * 16 + qrow;
        int r1 = r0 + 8;
        float t0 = g_saf[r0], t1 = g_saf[r1];
        float* p0 = out + (size_t)r0 * C_CLASSES + n0 + wn * 64 + qcol;
        float* p1 = out + (size_t)r1 * C_CLASSES + n0 + wn * 64 + qcol;
#pragma unroll
        for (int nf = 0; nf < 8; nf++) {
            int coln = n0 + wn * 64 + qcol + nf * 8;
            float sb0 = g_sbf[coln];
            float sb1 = g_sbf[coln + 1];
            float f00 = fmaf(16384.f, (float)hh[mt][nf][0], 128.f * (float)mx[mt][nf][0]);
            float f01 = fmaf(16384.f, (float)hh[mt][nf][1], 128.f * (float)mx[mt][nf][1]);
            float f10 = fmaf(16384.f, (float)hh[mt][nf][2], 128.f * (float)mx[mt][nf][2]);
            float f11 = fmaf(16384.f, (float)hh[mt][nf][3], 128.f * (float)mx[mt][nf][3]);
            float2 v0, v1;
            v0.x = f00 * t0 * sb0; v0.y = f01 * t0 * sb1;
            v1.x = f10 * t1 * sb0; v1.y = f11 * t1 * sb1;
            *(float2*)(p0 + nf * 8) = v0;
            *(float2*)(p1 + nf * 8) = v1;
        }
    }
}

// ---------------- launch ----------------
extern "C" void kernel_launch(void* const* d_in, const int* in_sizes, int n_in,
                              void* d_out, int out_size) {
    const float* ctx    = (const float*)d_in[0];
    const int*   labels = (const int*)d_in[1];
    const float* tgt    = (const float*)d_in[2];
    const int n_ctx = in_sizes[1];
    const int n_tgt = in_sizes[2] / DDIM;

    float* logits    = (float*)d_out;
    float* means_out = (float*)d_out + (size_t)n_tgt * C_CLASSES;

    cudaFuncSetAttribute(gemm_imma_kernel, cudaFuncAttributeMaxDynamicSharedMemorySize, SMEM_BYTES);

    zero_kernel<<<1, C_CLASSES>>>();
    count_kernel<<<64, 256>>>(labels, n_ctx);
    scan_kernel<<<1, C_CLASSES>>>();
    scatter_kernel<<<(n_ctx + 255) / 256, 256>>>(labels, n_ctx);
    classsum_kernel<<<dim3(C_CLASSES, DDIM / 256), 256>>>(ctx);
    finalize_kernel<<<C_CLASSES, 256>>>(means_out);
    quant_a_kernel<<<(n_tgt + 7) / 8, 256>>>((const float4*)tgt, n_tgt);
    gemm_imma_kernel<<<dim3(C_CLASSES / NT, n_tgt / MT), 256, SMEM_BYTES>>>(logits);
}

// round 6
// speedup vs baseline: 2.4477x; 2.4477x over previous
#include <cuda_runtime.h>
#include <cuda_bf16.h>
#include <math.h>
#include <stdint.h>

#define C_CLASSES 512
#define DDIM      1024
#define EPS_F     1e-30f
#define SCALE_F   50.0f
#define MAX_N     65536

// ---------------- scratch (device globals; no allocations allowed) ----------------
__device__ float         g_sums[C_CLASSES * DDIM];
__device__ __nv_bfloat16 g_bhi[C_CLASSES * DDIM];   // scaled means, hi bf16, [N][K]
__device__ __nv_bfloat16 g_blo[C_CLASSES * DDIM];   // scaled means, lo bf16, [N][K]
__device__ __nv_bfloat16 g_ahi[(size_t)MAX_N * DDIM];
__device__ __nv_bfloat16 g_alo[(size_t)MAX_N * DDIM];
__device__ float         g_tinv[MAX_N];
__device__ int           g_counts_i[C_CLASSES];
__device__ int           g_cursor[C_CLASSES];
__device__ int           g_offsets[C_CLASSES + 1];
__device__ int           g_idx[MAX_N];

// ---------------- PTX helpers (sm_80+ baseline features only) ----------------
__device__ __forceinline__ uint32_t smem_u32(const void* p) {
    uint32_t a;
    asm("{ .reg .u64 t; cvta.to.shared.u64 t, %1; cvt.u32.u64 %0, t; }" : "=r"(a) : "l"(p));
    return a;
}
#define CP_ASYNC16(dst, src) \
    asm volatile("cp.async.cg.shared.global [%0], [%1], 16;" :: "r"((uint32_t)(dst)), "l"(src))
#define CP_COMMIT() asm volatile("cp.async.commit_group;" ::: "memory")
#define CP_WAIT(n)  asm volatile("cp.async.wait_group %0;" :: "n"(n) : "memory")

__device__ __forceinline__ void ldsm_x4(uint32_t* r, uint32_t addr) {
    asm volatile("ldmatrix.sync.aligned.m8n8.x4.shared.b16 {%0,%1,%2,%3}, [%4];"
                 : "=r"(r[0]), "=r"(r[1]), "=r"(r[2]), "=r"(r[3]) : "r"(addr));
}
__device__ __forceinline__ void mma16816(float* c, const uint32_t* a, const uint32_t* b) {
    asm volatile("mma.sync.aligned.m16n8k16.row.col.f32.bf16.bf16.f32 "
                 "{%0,%1,%2,%3}, {%4,%5,%6,%7}, {%8,%9}, {%0,%1,%2,%3};"
                 : "+f"(c[0]), "+f"(c[1]), "+f"(c[2]), "+f"(c[3])
                 : "r"(a[0]), "r"(a[1]), "r"(a[2]), "r"(a[3]), "r"(b[0]), "r"(b[1]));
}

// ---------------- zero counts ----------------
__global__ void zero_kernel() {
    int i = threadIdx.x;
    if (i < C_CLASSES) g_counts_i[i] = 0;
}

// ---------------- histogram of labels ----------------
__global__ void count_kernel(const int* __restrict__ labels, int n) {
    __shared__ int hist[C_CLASSES];
    for (int i = threadIdx.x; i < C_CLASSES; i += blockDim.x) hist[i] = 0;
    __syncthreads();
    for (int i = blockIdx.x * blockDim.x + threadIdx.x; i < n; i += gridDim.x * blockDim.x)
        atomicAdd(&hist[labels[i]], 1);
    __syncthreads();
    for (int i = threadIdx.x; i < C_CLASSES; i += blockDim.x) {
        int v = hist[i];
        if (v) atomicAdd(&g_counts_i[i], v);
    }
}

// ---------------- exclusive scan over 512 counts ----------------
__global__ void scan_kernel() {
    __shared__ int tmp[C_CLASSES];
    int t = threadIdx.x;
    int v = g_counts_i[t];
    tmp[t] = v;
    __syncthreads();
    for (int off = 1; off < C_CLASSES; off <<= 1) {
        int x = (t >= off) ? tmp[t - off] : 0;
        __syncthreads();
        tmp[t] += x;
        __syncthreads();
    }
    g_offsets[t] = tmp[t] - v;
    g_cursor[t]  = tmp[t] - v;
    if (t == C_CLASSES - 1) g_offsets[C_CLASSES] = tmp[t];
}

// ---------------- scatter row indices into class buckets ----------------
__global__ void scatter_kernel(const int* __restrict__ labels, int n) {
    int i = blockIdx.x * blockDim.x + threadIdx.x;
    if (i < n) {
        int p = atomicAdd(&g_cursor[labels[i]], 1);
        g_idx[p] = i;
    }
}

// ---------------- per-class gather + register accumulation ----------------
__global__ void classsum_kernel(const float* __restrict__ ctx) {
    const int c   = blockIdx.x;
    const int col = blockIdx.y * 256 + threadIdx.x;
    const int beg = g_offsets[c];
    const int end = g_offsets[c + 1];

    float a0 = 0.f, a1 = 0.f, a2 = 0.f, a3 = 0.f;
    int i = beg;
    for (; i + 3 < end; i += 4) {
        int r0 = g_idx[i], r1 = g_idx[i + 1], r2 = g_idx[i + 2], r3 = g_idx[i + 3];
        a0 += ctx[(size_t)r0 * DDIM + col];
        a1 += ctx[(size_t)r1 * DDIM + col];
        a2 += ctx[(size_t)r2 * DDIM + col];
        a3 += ctx[(size_t)r3 * DDIM + col];
    }
    for (; i < end; i++) a0 += ctx[(size_t)g_idx[i] * DDIM + col];
    g_sums[(size_t)c * DDIM + col] = (a0 + a1) + (a2 + a3);
}

// ---------------- finalize: means -> d_out; scaled bf16 hi/lo B -> g_bhi/g_blo ----------------
__global__ void finalize_kernel(float* __restrict__ means_out) {
    const int c   = blockIdx.x;
    const int tid = threadIdx.x;
    const float inv = 1.f / fmaxf((float)g_counts_i[c], 1.f);

    float m[4];
    float ss = 0.f;
#pragma unroll
    for (int j = 0; j < 4; j++) {
        int d = tid + 256 * j;
        float v = g_sums[(size_t)c * DDIM + d] * inv;
        m[j] = v;
        means_out[(size_t)c * DDIM + d] = v;
        ss += v * v;
    }
    __shared__ float red[8];
#pragma unroll
    for (int o = 16; o > 0; o >>= 1) ss += __shfl_xor_sync(0xffffffffu, ss, o);
    if ((tid & 31) == 0) red[tid >> 5] = ss;
    __syncthreads();
    __shared__ float s_scale;
    if (tid == 0) {
        float tot = 0.f;
#pragma unroll
        for (int k = 0; k < 8; k++) tot += red[k];
        s_scale = SCALE_F / fmaxf(sqrtf(tot), EPS_F);
    }
    __syncthreads();
    const float sc = s_scale;
#pragma unroll
    for (int j = 0; j < 4; j++) {
        int d = tid + 256 * j;
        float s = m[j] * sc;
        __nv_bfloat16 h = __float2bfloat16_rn(s);
        g_bhi[(size_t)c * DDIM + d] = h;
        g_blo[(size_t)c * DDIM + d] = __float2bfloat16_rn(s - __bfloat162float(h));
    }
}

// ---------------- fused: target bf16 hi/lo split + inverse norms (one warp per row) ----------------
__global__ void split_tinv_kernel(const float4* __restrict__ tgt4, int n_tgt) {
    int w    = (blockIdx.x * blockDim.x + threadIdx.x) >> 5;
    int lane = threadIdx.x & 31;
    if (w >= n_tgt) return;
    const float4* row = tgt4 + (size_t)w * (DDIM / 4);
    uint2* hrow = (uint2*)(g_ahi + (size_t)w * DDIM);
    uint2* lrow = (uint2*)(g_alo + (size_t)w * DDIM);
    float ss = 0.f;
#pragma unroll
    for (int j = 0; j < 8; j++) {
        int e4 = lane + 32 * j;
        float4 v = row[e4];
        ss += v.x * v.x + v.y * v.y + v.z * v.z + v.w * v.w;
        __nv_bfloat162 h0 = __floats2bfloat162_rn(v.x, v.y);
        __nv_bfloat162 h1 = __floats2bfloat162_rn(v.z, v.w);
        float2 f0 = __bfloat1622float2(h0);
        float2 f1 = __bfloat1622float2(h1);
        __nv_bfloat162 l0 = __floats2bfloat162_rn(v.x - f0.x, v.y - f0.y);
        __nv_bfloat162 l1 = __floats2bfloat162_rn(v.z - f1.x, v.w - f1.y);
        uint2 hu, lu;
        hu.x = *reinterpret_cast<uint32_t*>(&h0);
        hu.y = *reinterpret_cast<uint32_t*>(&h1);
        lu.x = *reinterpret_cast<uint32_t*>(&l0);
        lu.y = *reinterpret_cast<uint32_t*>(&l1);
        hrow[e4] = hu;
        lrow[e4] = lu;
    }
#pragma unroll
    for (int o = 16; o > 0; o >>= 1) ss += __shfl_xor_sync(0xffffffffu, ss, o);
    if (lane == 0) g_tinv[w] = 1.f / fmaxf(sqrtf(ss), EPS_F);
}

// ---------------- bf16x3 HMMA GEMM: out[M,512] = (Ahi+Alo)(Bhi+Blo)^T * tinv ----------------
// CTA tile 128x256, 512 threads, 16 warps (4m x 4n), warp tile 32x64.
// K-chunk 32 (64B rows padded to 80B -> conflict-free ldmatrix, no swizzle), 3 stages.
#define MT   128
#define NT   256
#define KC   32
#define NC   (DDIM / KC)             // 32
#define ROWB 80                      // padded row pitch (bytes) for 64B of data
#define OFF_AHI  0
#define OFF_ALO  10240
#define OFF_BHI  20480
#define OFF_BLO  40960
#define STAGE    61440
#define NSTAGE   3
#define SMEM_BYTES (NSTAGE * STAGE + 1024)

__device__ __forceinline__ void load_chunk(uint32_t stage, int m0, int n0, int gk0, int tid) {
    // A: 128 rows x 4 x 16B (hi & lo) -> 512 chunks each, 1 per thread
    {
        int row = tid >> 2, c = tid & 3;
        size_t gsrc = (size_t)(m0 + row) * DDIM + gk0;
        uint32_t off = (uint32_t)row * ROWB + (uint32_t)c * 16;
        CP_ASYNC16(stage + OFF_AHI + off, (const char*)(g_ahi + gsrc) + c * 16);
        CP_ASYNC16(stage + OFF_ALO + off, (const char*)(g_alo + gsrc) + c * 16);
    }
    // B: 256 rows x 4 x 16B (hi & lo) -> 1024 chunks each, 2 per thread
#pragma unroll
    for (int p = 0; p < 2; p++) {
        int i = tid + p * 512;
        int row = i >> 2, c = i & 3;
        size_t gsrc = (size_t)(n0 + row) * DDIM + gk0;
        uint32_t off = (uint32_t)row * ROWB + (uint32_t)c * 16;
        CP_ASYNC16(stage + OFF_BHI + off, (const char*)(g_bhi + gsrc) + c * 16);
        CP_ASYNC16(stage + OFF_BLO + off, (const char*)(g_blo + gsrc) + c * 16);
    }
    CP_COMMIT();
}

__global__ void __launch_bounds__(512, 1) gemm_mma_kernel(float* __restrict__ out) {
    extern __shared__ char dsm[];
    uint32_t sb = (smem_u32(dsm) + 1023) & ~1023u;

    const int tid  = threadIdx.x;
    const int wid  = tid >> 5;
    const int lane = tid & 31;
    const int wm   = wid >> 2;            // 0..3 (m)
    const int wn   = wid & 3;             // 0..3 (n)
    const int n0 = blockIdx.x * NT;
    const int m0 = blockIdx.y * MT;

    float acc[2][8][4];
#pragma unroll
    for (int a = 0; a < 2; a++)
#pragma unroll
        for (int b = 0; b < 8; b++)
#pragma unroll
            for (int c = 0; c < 4; c++) acc[a][b][c] = 0.f;

    // prologue: 2 chunks in flight
    load_chunk(sb + 0 * STAGE, m0, n0, 0, tid);
    load_chunk(sb + 1 * STAGE, m0, n0, KC, tid);

    // lane pieces
    const int a_r  = (lane & 15);
    const int a_kh = (lane >> 4);
    const int b_r  = (lane & 7) + ((lane >> 4) << 3);
    const int b_kh = (lane >> 3) & 1;

    int stg = 0;
    for (int c = 0; c < NC; c++) {
        if (c < NC - 1) CP_WAIT(1); else CP_WAIT(0);
        __syncthreads();
        uint32_t stage = sb + (uint32_t)stg * STAGE;

#pragma unroll
        for (int s = 0; s < 2; s++) {     // 2 k16 slices per 32-wide chunk
            uint32_t ah[2][4], al[2][4], bh[4][4], bl[4][4];
#pragma unroll
            for (int mt = 0; mt < 2; mt++) {
                int row = wm * 32 + mt * 16 + a_r;
                uint32_t off = (uint32_t)row * ROWB + (uint32_t)(s * 2 + a_kh) * 16;
                ldsm_x4(ah[mt], stage + OFF_AHI + off);
                ldsm_x4(al[mt], stage + OFF_ALO + off);
            }
#pragma unroll
            for (int nt = 0; nt < 4; nt++) {
                int row = wn * 64 + nt * 16 + b_r;
                uint32_t off = (uint32_t)row * ROWB + (uint32_t)(s * 2 + b_kh) * 16;
                ldsm_x4(bh[nt], stage + OFF_BHI + off);
                ldsm_x4(bl[nt], stage + OFF_BLO + off);
            }
            // pass 1: hi*hi — 16 independent MMAs (acc reuse distance = 16)
#pragma unroll
            for (int mt = 0; mt < 2; mt++)
#pragma unroll
                for (int nt = 0; nt < 4; nt++) {
                    mma16816(acc[mt][nt * 2 + 0], ah[mt], &bh[nt][0]);
                    mma16816(acc[mt][nt * 2 + 1], ah[mt], &bh[nt][2]);
                }
            // pass 2: lo*hi
#pragma unroll
            for (int mt = 0; mt < 2; mt++)
#pragma unroll
                for (int nt = 0; nt < 4; nt++) {
                    mma16816(acc[mt][nt * 2 + 0], al[mt], &bh[nt][0]);
                    mma16816(acc[mt][nt * 2 + 1], al[mt], &bh[nt][2]);
                }
            // pass 3: hi*lo
#pragma unroll
            for (int mt = 0; mt < 2; mt++)
#pragma unroll
                for (int nt = 0; nt < 4; nt++) {
                    mma16816(acc[mt][nt * 2 + 0], ah[mt], &bl[nt][0]);
                    mma16816(acc[mt][nt * 2 + 1], ah[mt], &bl[nt][2]);
                }
        }

        if (c + 2 < NC) {
            int nstg = stg + 2; if (nstg >= NSTAGE) nstg -= NSTAGE;
            load_chunk(sb + (uint32_t)nstg * STAGE, m0, n0, (c + 2) * KC, tid);
        }
        if (++stg == NSTAGE) stg = 0;
    }

    // epilogue: scale by 1/||t|| and store
    const int qrow = lane >> 2;
    const int qcol = (lane & 3) * 2;
#pragma unroll
    for (int mt = 0; mt < 2; mt++) {
        int r0 = m0 + wm * 32 + mt * 16 + qrow;
        int r1 = r0 + 8;
        float t0 = g_tinv[r0], t1 = g_tinv[r1];
        float* p0 = out + (size_t)r0 * C_CLASSES + n0 + wn * 64 + qcol;
        float* p1 = out + (size_t)r1 * C_CLASSES + n0 + wn * 64 + qcol;
#pragma unroll
        for (int nf = 0; nf < 8; nf++) {
            float2 v0, v1;
            v0.x = acc[mt][nf][0] * t0; v0.y = acc[mt][nf][1] * t0;
            v1.x = acc[mt][nf][2] * t1; v1.y = acc[mt][nf][3] * t1;
            *(float2*)(p0 + nf * 8) = v0;
            *(float2*)(p1 + nf * 8) = v1;
        }
    }
}

// ---------------- launch (side-stream fork/join for prep overlap) ----------------
extern "C" void kernel_launch(void* const* d_in, const int* in_sizes, int n_in,
                              void* d_out, int out_size) {
    const float* ctx    = (const float*)d_in[0];
    const int*   labels = (const int*)d_in[1];
    const float* tgt    = (const float*)d_in[2];
    const int n_ctx = in_sizes[1];
    const int n_tgt = in_sizes[2] / DDIM;

    float* logits    = (float*)d_out;
    float* means_out = (float*)d_out + (size_t)n_tgt * C_CLASSES;

    static cudaStream_t s_side = nullptr;
    static cudaEvent_t  s_fork = nullptr, s_join = nullptr;
    if (!s_side) {
        cudaStreamCreateWithFlags(&s_side, cudaStreamNonBlocking);
        cudaEventCreateWithFlags(&s_fork, cudaEventDisableTiming);
        cudaEventCreateWithFlags(&s_join, cudaEventDisableTiming);
    }
    cudaFuncSetAttribute(gemm_mma_kernel, cudaFuncAttributeMaxDynamicSharedMemorySize, SMEM_BYTES);

    // fork: target split runs concurrently with the class-means chain
    cudaEventRecord(s_fork, 0);
    cudaStreamWaitEvent(s_side, s_fork, 0);
    split_tinv_kernel<<<(n_tgt + 7) / 8, 256, 0, s_side>>>((const float4*)tgt, n_tgt);
    cudaEventRecord(s_join, s_side);

    zero_kernel<<<1, C_CLASSES>>>();
    count_kernel<<<64, 256>>>(labels, n_ctx);
    scan_kernel<<<1, C_CLASSES>>>();
    scatter_kernel<<<(n_ctx + 255) / 256, 256>>>(labels, n_ctx);
    classsum_kernel<<<dim3(C_CLASSES, DDIM / 256), 256>>>(ctx);
    finalize_kernel<<<C_CLASSES, 256>>>(means_out);

    // join: GEMM needs both branches
    cudaStreamWaitEvent(0, s_join, 0);
    gemm_mma_kernel<<<dim3(C_CLASSES / NT, n_tgt / MT), 512, SMEM_BYTES>>>(logits);
}

// round 7
// speedup vs baseline: 2.5779x; 1.0532x over previous
#include <cuda_runtime.h>
#include <cuda_bf16.h>
#include <math.h>
#include <stdint.h>

#define C_CLASSES 512
#define DDIM      1024
#define EPS_F     1e-30f
#define SCALE_F   50.0f
#define MAX_N     65536

// ---------------- scratch (device globals; no allocations allowed) ----------------
__device__ float         g_sums[C_CLASSES * DDIM];
__device__ __nv_bfloat16 g_bhi[C_CLASSES * DDIM];   // scaled means, hi bf16, [N][K]
__device__ __nv_bfloat16 g_blo[C_CLASSES * DDIM];   // scaled means, lo bf16, [N][K]
__device__ __nv_bfloat16 g_ahi[(size_t)MAX_N * DDIM];
__device__ __nv_bfloat16 g_alo[(size_t)MAX_N * DDIM];
__device__ float         g_tinv[MAX_N];
__device__ int           g_counts_i[C_CLASSES];
__device__ int           g_cursor[C_CLASSES];
__device__ int           g_offsets[C_CLASSES + 1];
__device__ int           g_idx[MAX_N];

// ---------------- PTX helpers (sm_80+ baseline features only) ----------------
__device__ __forceinline__ uint32_t smem_u32(const void* p) {
    uint32_t a;
    asm("{ .reg .u64 t; cvta.to.shared.u64 t, %1; cvt.u32.u64 %0, t; }" : "=r"(a) : "l"(p));
    return a;
}
#define CP_ASYNC16(dst, src) \
    asm volatile("cp.async.cg.shared.global [%0], [%1], 16;" :: "r"((uint32_t)(dst)), "l"(src))
#define CP_COMMIT() asm volatile("cp.async.commit_group;" ::: "memory")
#define CP_WAIT(n)  asm volatile("cp.async.wait_group %0;" :: "n"(n) : "memory")

__device__ __forceinline__ void ldsm_x4(uint32_t* r, uint32_t addr) {
    asm volatile("ldmatrix.sync.aligned.m8n8.x4.shared.b16 {%0,%1,%2,%3}, [%4];"
                 : "=r"(r[0]), "=r"(r[1]), "=r"(r[2]), "=r"(r[3]) : "r"(addr));
}
__device__ __forceinline__ void mma16816(float* c, const uint32_t* a, const uint32_t* b) {
    asm volatile("mma.sync.aligned.m16n8k16.row.col.f32.bf16.bf16.f32 "
                 "{%0,%1,%2,%3}, {%4,%5,%6,%7}, {%8,%9}, {%0,%1,%2,%3};"
                 : "+f"(c[0]), "+f"(c[1]), "+f"(c[2]), "+f"(c[3])
                 : "r"(a[0]), "r"(a[1]), "r"(a[2]), "r"(a[3]), "r"(b[0]), "r"(b[1]));
}
// 64B-row tile swizzle: 16B column c (0..3) xored with (row>>1)&3 -> each
// ldmatrix 8-lane phase (8 consecutive rows, fixed c) hits 8 distinct 16B bank
// groups (row bit0 gives the 64B half, (row>>1)&3 permutes within it).
__device__ __forceinline__ uint32_t tile_off(int row, int c16) {
    return (uint32_t)row * 64 + (uint32_t)((c16 ^ ((row >> 1) & 3)) << 4);
}

// ---------------- zero counts ----------------
__global__ void zero_kernel() {
    int i = threadIdx.x;
    if (i < C_CLASSES) g_counts_i[i] = 0;
}

// ---------------- histogram of labels ----------------
__global__ void count_kernel(const int* __restrict__ labels, int n) {
    __shared__ int hist[C_CLASSES];
    for (int i = threadIdx.x; i < C_CLASSES; i += blockDim.x) hist[i] = 0;
    __syncthreads();
    for (int i = blockIdx.x * blockDim.x + threadIdx.x; i < n; i += gridDim.x * blockDim.x)
        atomicAdd(&hist[labels[i]], 1);
    __syncthreads();
    for (int i = threadIdx.x; i < C_CLASSES; i += blockDim.x) {
        int v = hist[i];
        if (v) atomicAdd(&g_counts_i[i], v);
    }
}

// ---------------- exclusive scan over 512 counts ----------------
__global__ void scan_kernel() {
    __shared__ int tmp[C_CLASSES];
    int t = threadIdx.x;
    int v = g_counts_i[t];
    tmp[t] = v;
    __syncthreads();
    for (int off = 1; off < C_CLASSES; off <<= 1) {
        int x = (t >= off) ? tmp[t - off] : 0;
        __syncthreads();
        tmp[t] += x;
        __syncthreads();
    }
    g_offsets[t] = tmp[t] - v;
    g_cursor[t]  = tmp[t] - v;
    if (t == C_CLASSES - 1) g_offsets[C_CLASSES] = tmp[t];
}

// ---------------- scatter row indices into class buckets ----------------
__global__ void scatter_kernel(const int* __restrict__ labels, int n) {
    int i = blockIdx.x * blockDim.x + threadIdx.x;
    if (i < n) {
        int p = atomicAdd(&g_cursor[labels[i]], 1);
        g_idx[p] = i;
    }
}

// ---------------- per-class gather + register accumulation ----------------
__global__ void classsum_kernel(const float* __restrict__ ctx) {
    const int c   = blockIdx.x;
    const int col = blockIdx.y * 256 + threadIdx.x;
    const int beg = g_offsets[c];
    const int end = g_offsets[c + 1];

    float a0 = 0.f, a1 = 0.f, a2 = 0.f, a3 = 0.f;
    int i = beg;
    for (; i + 3 < end; i += 4) {
        int r0 = g_idx[i], r1 = g_idx[i + 1], r2 = g_idx[i + 2], r3 = g_idx[i + 3];
        a0 += ctx[(size_t)r0 * DDIM + col];
        a1 += ctx[(size_t)r1 * DDIM + col];
        a2 += ctx[(size_t)r2 * DDIM + col];
        a3 += ctx[(size_t)r3 * DDIM + col];
    }
    for (; i < end; i++) a0 += ctx[(size_t)g_idx[i] * DDIM + col];
    g_sums[(size_t)c * DDIM + col] = (a0 + a1) + (a2 + a3);
}

// ---------------- finalize: means -> d_out; scaled bf16 hi/lo B -> g_bhi/g_blo ----------------
__global__ void finalize_kernel(float* __restrict__ means_out) {
    const int c   = blockIdx.x;
    const int tid = threadIdx.x;
    const float inv = 1.f / fmaxf((float)g_counts_i[c], 1.f);

    float m[4];
    float ss = 0.f;
#pragma unroll
    for (int j = 0; j < 4; j++) {
        int d = tid + 256 * j;
        float v = g_sums[(size_t)c * DDIM + d] * inv;
        m[j] = v;
        means_out[(size_t)c * DDIM + d] = v;
        ss += v * v;
    }
    __shared__ float red[8];
#pragma unroll
    for (int o = 16; o > 0; o >>= 1) ss += __shfl_xor_sync(0xffffffffu, ss, o);
    if ((tid & 31) == 0) red[tid >> 5] = ss;
    __syncthreads();
    __shared__ float s_scale;
    if (tid == 0) {
        float tot = 0.f;
#pragma unroll
        for (int k = 0; k < 8; k++) tot += red[k];
        s_scale = SCALE_F / fmaxf(sqrtf(tot), EPS_F);
    }
    __syncthreads();
    const float sc = s_scale;
#pragma unroll
    for (int j = 0; j < 4; j++) {
        int d = tid + 256 * j;
        float s = m[j] * sc;
        __nv_bfloat16 h = __float2bfloat16_rn(s);
        g_bhi[(size_t)c * DDIM + d] = h;
        g_blo[(size_t)c * DDIM + d] = __float2bfloat16_rn(s - __bfloat162float(h));
    }
}

// ---------------- fused: target bf16 hi/lo split + inverse norms (one warp per row) ----------------
__global__ void split_tinv_kernel(const float4* __restrict__ tgt4, int n_tgt) {
    int w    = (blockIdx.x * blockDim.x + threadIdx.x) >> 5;
    int lane = threadIdx.x & 31;
    if (w >= n_tgt) return;
    const float4* row = tgt4 + (size_t)w * (DDIM / 4);
    uint2* hrow = (uint2*)(g_ahi + (size_t)w * DDIM);
    uint2* lrow = (uint2*)(g_alo + (size_t)w * DDIM);
    float ss = 0.f;
#pragma unroll
    for (int j = 0; j < 8; j++) {
        int e4 = lane + 32 * j;
        float4 v = row[e4];
        ss += v.x * v.x + v.y * v.y + v.z * v.z + v.w * v.w;
        __nv_bfloat162 h0 = __floats2bfloat162_rn(v.x, v.y);
        __nv_bfloat162 h1 = __floats2bfloat162_rn(v.z, v.w);
        float2 f0 = __bfloat1622float2(h0);
        float2 f1 = __bfloat1622float2(h1);
        __nv_bfloat162 l0 = __floats2bfloat162_rn(v.x - f0.x, v.y - f0.y);
        __nv_bfloat162 l1 = __floats2bfloat162_rn(v.z - f1.x, v.w - f1.y);
        uint2 hu, lu;
        hu.x = *reinterpret_cast<uint32_t*>(&h0);
        hu.y = *reinterpret_cast<uint32_t*>(&h1);
        lu.x = *reinterpret_cast<uint32_t*>(&l0);
        lu.y = *reinterpret_cast<uint32_t*>(&l1);
        hrow[e4] = hu;
        lrow[e4] = lu;
    }
#pragma unroll
    for (int o = 16; o > 0; o >>= 1) ss += __shfl_xor_sync(0xffffffffu, ss, o);
    if (lane == 0) g_tinv[w] = 1.f / fmaxf(sqrtf(ss), EPS_F);
}

// ---------------- bf16x3 HMMA GEMM: out[M,512] = (Ahi+Alo)(Bhi+Blo)^T * tinv ----------------
// CTA tile 128x128, 256 threads, 8 warps (4m x 2n), warp tile 32x64.
// K-chunk 32 (64B rows, swizzled), 3 stages of 32KB -> 2 CTAs/SM.
#define MT   128
#define NT   128
#define KC   32
#define NC   (DDIM / KC)             // 32
#define OFF_AHI  0
#define OFF_ALO  8192
#define OFF_BHI  16384
#define OFF_BLO  24576
#define STAGE    32768
#define NSTAGE   3
#define SMEM_BYTES (NSTAGE * STAGE + 1024)

__device__ __forceinline__ void load_chunk(uint32_t stage, int m0, int n0, int gk0, int tid) {
#pragma unroll
    for (int p = 0; p < 2; p++) {
        int i = tid + p * 256;
        int row = i >> 2, c = i & 3;
        uint32_t off = tile_off(row, c);
        size_t gsrc = (size_t)(m0 + row) * DDIM + gk0 + c * 8;
        CP_ASYNC16(stage + OFF_AHI + off, (const char*)(g_ahi + gsrc));
        CP_ASYNC16(stage + OFF_ALO + off, (const char*)(g_alo + gsrc));
    }
#pragma unroll
    for (int p = 0; p < 2; p++) {
        int i = tid + p * 256;
        int row = i >> 2, c = i & 3;
        uint32_t off = tile_off(row, c);
        size_t gsrc = (size_t)(n0 + row) * DDIM + gk0 + c * 8;
        CP_ASYNC16(stage + OFF_BHI + off, (const char*)(g_bhi + gsrc));
        CP_ASYNC16(stage + OFF_BLO + off, (const char*)(g_blo + gsrc));
    }
    CP_COMMIT();
}

__global__ void __launch_bounds__(256, 2) gemm_mma_kernel(float* __restrict__ out) {
    extern __shared__ char dsm[];
    uint32_t sb = (smem_u32(dsm) + 1023) & ~1023u;

    const int tid  = threadIdx.x;
    const int wid  = tid >> 5;
    const int lane = tid & 31;
    const int wm   = wid >> 1;            // 0..3 (m)
    const int wn   = wid & 1;             // 0..1 (n)
    const int n0 = blockIdx.x * NT;
    const int m0 = blockIdx.y * MT;

    float acc[2][8][4];
#pragma unroll
    for (int a = 0; a < 2; a++)
#pragma unroll
        for (int b = 0; b < 8; b++)
#pragma unroll
            for (int c = 0; c < 4; c++) acc[a][b][c] = 0.f;

    // prologue: 2 chunks in flight
    load_chunk(sb + 0 * STAGE, m0, n0, 0, tid);
    load_chunk(sb + 1 * STAGE, m0, n0, KC, tid);

    // lane pieces
    const int a_r  = (lane & 15);
    const int a_kh = (lane >> 4);
    const int b_r  = (lane & 7) + ((lane >> 4) << 3);
    const int b_kh = (lane >> 3) & 1;

    int stg = 0;
    for (int c = 0; c < NC; c++) {
        if (c < NC - 1) CP_WAIT(1); else CP_WAIT(0);
        __syncthreads();
        uint32_t stage = sb + (uint32_t)stg * STAGE;

#pragma unroll
        for (int s = 0; s < 2; s++) {     // 2 k16 slices per 32-wide chunk
            uint32_t ah[2][4], al[2][4], bh[4][4], bl[4][4];
#pragma unroll
            for (int mt = 0; mt < 2; mt++) {
                int row = wm * 32 + mt * 16 + a_r;
                uint32_t off = tile_off(row, s * 2 + a_kh);
                ldsm_x4(ah[mt], stage + OFF_AHI + off);
                ldsm_x4(al[mt], stage + OFF_ALO + off);
            }
#pragma unroll
            for (int nt = 0; nt < 4; nt++) {
                int row = wn * 64 + nt * 16 + b_r;
                uint32_t off = tile_off(row, s * 2 + b_kh);
                ldsm_x4(bh[nt], stage + OFF_BHI + off);
                ldsm_x4(bl[nt], stage + OFF_BLO + off);
            }
            // pass 1: hi*hi — 16 independent MMAs (acc reuse distance = 16)
#pragma unroll
            for (int mt = 0; mt < 2; mt++)
#pragma unroll
                for (int nt = 0; nt < 4; nt++) {
                    mma16816(acc[mt][nt * 2 + 0], ah[mt], &bh[nt][0]);
                    mma16816(acc[mt][nt * 2 + 1], ah[mt], &bh[nt][2]);
                }
            // pass 2: lo*hi
#pragma unroll
            for (int mt = 0; mt < 2; mt++)
#pragma unroll
                for (int nt = 0; nt < 4; nt++) {
                    mma16816(acc[mt][nt * 2 + 0], al[mt], &bh[nt][0]);
                    mma16816(acc[mt][nt * 2 + 1], al[mt], &bh[nt][2]);
                }
            // pass 3: hi*lo
#pragma unroll
            for (int mt = 0; mt < 2; mt++)
#pragma unroll
                for (int nt = 0; nt < 4; nt++) {
                    mma16816(acc[mt][nt * 2 + 0], ah[mt], &bl[nt][0]);
                    mma16816(acc[mt][nt * 2 + 1], ah[mt], &bl[nt][2]);
                }
        }

        if (c + 2 < NC) {
            int nstg = stg + 2; if (nstg >= NSTAGE) nstg -= NSTAGE;
            load_chunk(sb + (uint32_t)nstg * STAGE, m0, n0, (c + 2) * KC, tid);
        }
        if (++stg == NSTAGE) stg = 0;
    }

    // epilogue: scale by 1/||t|| and store
    const int qrow = lane >> 2;
    const int qcol = (lane & 3) * 2;
#pragma unroll
    for (int mt = 0; mt < 2; mt++) {
        int r0 = m0 + wm * 32 + mt * 16 + qrow;
        int r1 = r0 + 8;
        float t0 = g_tinv[r0], t1 = g_tinv[r1];
        float* p0 = out + (size_t)r0 * C_CLASSES + n0 + wn * 64 + qcol;
        float* p1 = out + (size_t)r1 * C_CLASSES + n0 + wn * 64 + qcol;
#pragma unroll
        for (int nf = 0; nf < 8; nf++) {
            float2 v0, v1;
            v0.x = acc[mt][nf][0] * t0; v0.y = acc[mt][nf][1] * t0;
            v1.x = acc[mt][nf][2] * t1; v1.y = acc[mt][nf][3] * t1;
            *(float2*)(p0 + nf * 8) = v0;
            *(float2*)(p1 + nf * 8) = v1;
        }
    }
}

// ---------------- launch (side-stream fork/join for prep overlap) ----------------
extern "C" void kernel_launch(void* const* d_in, const int* in_sizes, int n_in,
                              void* d_out, int out_size) {
    const float* ctx    = (const float*)d_in[0];
    const int*   labels = (const int*)d_in[1];
    const float* tgt    = (const float*)d_in[2];
    const int n_ctx = in_sizes[1];
    const int n_tgt = in_sizes[2] / DDIM;

    float* logits    = (float*)d_out;
    float* means_out = (float*)d_out + (size_t)n_tgt * C_CLASSES;

    static cudaStream_t s_side = nullptr;
    static cudaEvent_t  s_fork = nullptr, s_join = nullptr;
    if (!s_side) {
        cudaStreamCreateWithFlags(&s_side, cudaStreamNonBlocking);
        cudaEventCreateWithFlags(&s_fork, cudaEventDisableTiming);
        cudaEventCreateWithFlags(&s_join, cudaEventDisableTiming);
    }
    cudaFuncSetAttribute(gemm_mma_kernel, cudaFuncAttributeMaxDynamicSharedMemorySize, SMEM_BYTES);

    // fork: target split runs concurrently with the class-means chain
    cudaEventRecord(s_fork, 0);
    cudaStreamWaitEvent(s_side, s_fork, 0);
    split_tinv_kernel<<<(n_tgt + 7) / 8, 256, 0, s_side>>>((const float4*)tgt, n_tgt);
    cudaEventRecord(s_join, s_side);

    zero_kernel<<<1, C_CLASSES>>>();
    count_kernel<<<64, 256>>>(labels, n_ctx);
    scan_kernel<<<1, C_CLASSES>>>();
    scatter_kernel<<<(n_ctx + 255) / 256, 256>>>(labels, n_ctx);
    classsum_kernel<<<dim3(C_CLASSES, DDIM / 256), 256>>>(ctx);
    finalize_kernel<<<C_CLASSES, 256>>>(means_out);

    // join: GEMM needs both branches
    cudaStreamWaitEvent(0, s_join, 0);
    gemm_mma_kernel<<<dim3(C_CLASSES / NT, n_tgt / MT), 256, SMEM_BYTES>>>(logits);
}

// round 8
// speedup vs baseline: 5.0195x; 1.9471x over previous
#include <cuda_runtime.h>
#include <cuda_fp16.h>
#include <math.h>
#include <stdint.h>

#define C_CLASSES 512
#define DDIM      1024
#define EPS_F     1e-30f
#define SCALE_F   50.0f
#define MAX_N     65536

// ---------------- scratch (device globals; no allocations allowed) ----------------
__device__ float  g_sums[C_CLASSES * DDIM];
__device__ __half g_bh[C_CLASSES * DDIM];          // scaled means fp16, [N][K]
__device__ __half g_ah[(size_t)MAX_N * DDIM];      // targets fp16, [M][K]
__device__ float  g_tinv[MAX_N];
__device__ int    g_counts_i[C_CLASSES];
__device__ int    g_cursor[C_CLASSES];
__device__ int    g_offsets[C_CLASSES + 1];
__device__ int    g_idx[MAX_N];

// ---------------- PTX helpers (sm_80+ baseline features only) ----------------
__device__ __forceinline__ uint32_t smem_u32(const void* p) {
    uint32_t a;
    asm("{ .reg .u64 t; cvta.to.shared.u64 t, %1; cvt.u32.u64 %0, t; }" : "=r"(a) : "l"(p));
    return a;
}
#define CP_ASYNC16(dst, src) \
    asm volatile("cp.async.cg.shared.global [%0], [%1], 16;" :: "r"((uint32_t)(dst)), "l"(src))
#define CP_COMMIT() asm volatile("cp.async.commit_group;" ::: "memory")
#define CP_WAIT(n)  asm volatile("cp.async.wait_group %0;" :: "n"(n) : "memory")

__device__ __forceinline__ void ldsm_x4(uint32_t* r, uint32_t addr) {
    asm volatile("ldmatrix.sync.aligned.m8n8.x4.shared.b16 {%0,%1,%2,%3}, [%4];"
                 : "=r"(r[0]), "=r"(r[1]), "=r"(r[2]), "=r"(r[3]) : "r"(addr));
}
__device__ __forceinline__ void mma16816(float* c, const uint32_t* a, const uint32_t* b) {
    asm volatile("mma.sync.aligned.m16n8k16.row.col.f32.f16.f16.f32 "
                 "{%0,%1,%2,%3}, {%4,%5,%6,%7}, {%8,%9}, {%0,%1,%2,%3};"
                 : "+f"(c[0]), "+f"(c[1]), "+f"(c[2]), "+f"(c[3])
                 : "r"(a[0]), "r"(a[1]), "r"(a[2]), "r"(a[3]), "r"(b[0]), "r"(b[1]));
}
// 128B-row XOR swizzle: 16B column index c ^= (row & 7)
#define SWZ(o) ((o) ^ (((o) >> 3) & 0x70))

// ---------------- zero counts ----------------
__global__ void zero_kernel() {
    int i = threadIdx.x;
    if (i < C_CLASSES) g_counts_i[i] = 0;
}

// ---------------- histogram of labels ----------------
__global__ void count_kernel(const int* __restrict__ labels, int n) {
    __shared__ int hist[C_CLASSES];
    for (int i = threadIdx.x; i < C_CLASSES; i += blockDim.x) hist[i] = 0;
    __syncthreads();
    for (int i = blockIdx.x * blockDim.x + threadIdx.x; i < n; i += gridDim.x * blockDim.x)
        atomicAdd(&hist[labels[i]], 1);
    __syncthreads();
    for (int i = threadIdx.x; i < C_CLASSES; i += blockDim.x) {
        int v = hist[i];
        if (v) atomicAdd(&g_counts_i[i], v);
    }
}

// ---------------- exclusive scan over 512 counts ----------------
__global__ void scan_kernel() {
    __shared__ int tmp[C_CLASSES];
    int t = threadIdx.x;
    int v = g_counts_i[t];
    tmp[t] = v;
    __syncthreads();
    for (int off = 1; off < C_CLASSES; off <<= 1) {
        int x = (t >= off) ? tmp[t - off] : 0;
        __syncthreads();
        tmp[t] += x;
        __syncthreads();
    }
    g_offsets[t] = tmp[t] - v;
    g_cursor[t]  = tmp[t] - v;
    if (t == C_CLASSES - 1) g_offsets[C_CLASSES] = tmp[t];
}

// ---------------- scatter row indices into class buckets ----------------
__global__ void scatter_kernel(const int* __restrict__ labels, int n) {
    int i = blockIdx.x * blockDim.x + threadIdx.x;
    if (i < n) {
        int p = atomicAdd(&g_cursor[labels[i]], 1);
        g_idx[p] = i;
    }
}

// ---------------- per-class gather + register accumulation ----------------
__global__ void classsum_kernel(const float* __restrict__ ctx) {
    const int c   = blockIdx.x;
    const int col = blockIdx.y * 256 + threadIdx.x;
    const int beg = g_offsets[c];
    const int end = g_offsets[c + 1];

    float a0 = 0.f, a1 = 0.f, a2 = 0.f, a3 = 0.f;
    int i = beg;
    for (; i + 3 < end; i += 4) {
        int r0 = g_idx[i], r1 = g_idx[i + 1], r2 = g_idx[i + 2], r3 = g_idx[i + 3];
        a0 += ctx[(size_t)r0 * DDIM + col];
        a1 += ctx[(size_t)r1 * DDIM + col];
        a2 += ctx[(size_t)r2 * DDIM + col];
        a3 += ctx[(size_t)r3 * DDIM + col];
    }
    for (; i < end; i++) a0 += ctx[(size_t)g_idx[i] * DDIM + col];
    g_sums[(size_t)c * DDIM + col] = (a0 + a1) + (a2 + a3);
}

// ---------------- finalize: means -> d_out; scaled fp16 B -> g_bh ----------------
__global__ void finalize_kernel(float* __restrict__ means_out) {
    const int c   = blockIdx.x;
    const int tid = threadIdx.x;
    const float inv = 1.f / fmaxf((float)g_counts_i[c], 1.f);

    float m[4];
    float ss = 0.f;
#pragma unroll
    for (int j = 0; j < 4; j++) {
        int d = tid + 256 * j;
        float v = g_sums[(size_t)c * DDIM + d] * inv;
        m[j] = v;
        means_out[(size_t)c * DDIM + d] = v;
        ss += v * v;
    }
    __shared__ float red[8];
#pragma unroll
    for (int o = 16; o > 0; o >>= 1) ss += __shfl_xor_sync(0xffffffffu, ss, o);
    if ((tid & 31) == 0) red[tid >> 5] = ss;
    __syncthreads();
    __shared__ float s_scale;
    if (tid == 0) {
        float tot = 0.f;
#pragma unroll
        for (int k = 0; k < 8; k++) tot += red[k];
        s_scale = SCALE_F / fmaxf(sqrtf(tot), EPS_F);
    }
    __syncthreads();
    const float sc = s_scale;
#pragma unroll
    for (int j = 0; j < 4; j++) {
        int d = tid + 256 * j;
        g_bh[(size_t)c * DDIM + d] = __float2half_rn(m[j] * sc);
    }
}

// ---------------- fused: target fp16 convert + inverse norms (one warp per row) ----------------
__global__ void quant_a_kernel(const float4* __restrict__ tgt4, int n_tgt) {
    int w    = (blockIdx.x * blockDim.x + threadIdx.x) >> 5;
    int lane = threadIdx.x & 31;
    if (w >= n_tgt) return;
    const float4* row = tgt4 + (size_t)w * (DDIM / 4);
    uint2* hrow = (uint2*)(g_ah + (size_t)w * DDIM);
    float ss = 0.f;
#pragma unroll
    for (int j = 0; j < 8; j++) {
        int e4 = lane + 32 * j;
        float4 v = row[e4];
        ss += v.x * v.x + v.y * v.y + v.z * v.z + v.w * v.w;
        __half2 h0 = __floats2half2_rn(v.x, v.y);
        __half2 h1 = __floats2half2_rn(v.z, v.w);
        uint2 hu;
        hu.x = *reinterpret_cast<uint32_t*>(&h0);
        hu.y = *reinterpret_cast<uint32_t*>(&h1);
        hrow[e4] = hu;
    }
#pragma unroll
    for (int o = 16; o > 0; o >>= 1) ss += __shfl_xor_sync(0xffffffffu, ss, o);
    if (lane == 0) g_tinv[w] = 1.f / fmaxf(sqrtf(ss), EPS_F);
}

// ---------------- fp16 HMMA GEMM: out[M,512] = A B^T * tinv ----------------
// CTA tile 128x128, 256 threads, 8 warps (4m x 2n), warp tile 32x64.
// K-chunk 64 (128B rows, SW128 swizzle), 3 stages of 32KB -> 2 CTAs/SM.
#define MT   128
#define NT   128
#define KC   64
#define NC   (DDIM / KC)             // 16
#define OFF_A    0
#define OFF_B    16384
#define STAGE    32768
#define NSTAGE   3
#define SMEM_BYTES (NSTAGE * STAGE + 1024)

__device__ __forceinline__ void load_chunk(uint32_t stage, int m0, int n0, int gk0, int tid) {
#pragma unroll
    for (int p = 0; p < 4; p++) {
        int i = tid + p * 256;
        int row = i >> 3, c16 = i & 7;
        uint32_t off = SWZ((uint32_t)row * 128 + (uint32_t)c16 * 16);
        CP_ASYNC16(stage + OFF_A + off,
                   (const char*)(g_ah + (size_t)(m0 + row) * DDIM + gk0) + c16 * 16);
    }
#pragma unroll
    for (int p = 0; p < 4; p++) {
        int i = tid + p * 256;
        int row = i >> 3, c16 = i & 7;
        uint32_t off = SWZ((uint32_t)row * 128 + (uint32_t)c16 * 16);
        CP_ASYNC16(stage + OFF_B + off,
                   (const char*)(g_bh + (size_t)(n0 + row) * DDIM + gk0) + c16 * 16);
    }
    CP_COMMIT();
}

__global__ void __launch_bounds__(256, 2) gemm_mma_kernel(float* __restrict__ out) {
    extern __shared__ char dsm[];
    uint32_t sb = (smem_u32(dsm) + 1023) & ~1023u;

    const int tid  = threadIdx.x;
    const int wid  = tid >> 5;
    const int lane = tid & 31;
    const int wm   = wid >> 1;            // 0..3 (m)
    const int wn   = wid & 1;             // 0..1 (n)
    const int n0 = blockIdx.x * NT;
    const int m0 = blockIdx.y * MT;

    float acc[2][8][4];
#pragma unroll
    for (int a = 0; a < 2; a++)
#pragma unroll
        for (int b = 0; b < 8; b++)
#pragma unroll
            for (int c = 0; c < 4; c++) acc[a][b][c] = 0.f;

    // prologue: 2 chunks in flight
    load_chunk(sb + 0 * STAGE, m0, n0, 0, tid);
    load_chunk(sb + 1 * STAGE, m0, n0, KC, tid);

    // lane pieces
    const int a_r  = (lane & 15);
    const int a_kh = (lane >> 4);
    const int b_r  = (lane & 7) + ((lane >> 4) << 3);
    const int b_kh = (lane >> 3) & 1;

    int stg = 0;
    for (int c = 0; c < NC; c++) {
        if (c < NC - 1) CP_WAIT(1); else CP_WAIT(0);
        __syncthreads();
        uint32_t stage = sb + (uint32_t)stg * STAGE;

#pragma unroll
        for (int s = 0; s < 4; s++) {     // 4 k16 slices per 64-wide chunk
            uint32_t af[2][4], bf[4][4];
#pragma unroll
            for (int mt = 0; mt < 2; mt++) {
                int row = wm * 32 + mt * 16 + a_r;
                uint32_t c16 = (uint32_t)((s * 2 + a_kh) ^ (row & 7));
                ldsm_x4(af[mt], stage + OFF_A + (uint32_t)row * 128 + c16 * 16);
            }
#pragma unroll
            for (int nt = 0; nt < 4; nt++) {
                int row = wn * 64 + nt * 16 + b_r;
                uint32_t c16 = (uint32_t)((s * 2 + b_kh) ^ (row & 7));
                ldsm_x4(bf[nt], stage + OFF_B + (uint32_t)row * 128 + c16 * 16);
            }
            // 16 independent MMAs (acc reuse distance = 16)
#pragma unroll
            for (int mt = 0; mt < 2; mt++)
#pragma unroll
                for (int nt = 0; nt < 4; nt++) {
                    mma16816(acc[mt][nt * 2 + 0], af[mt], &bf[nt][0]);
                    mma16816(acc[mt][nt * 2 + 1], af[mt], &bf[nt][2]);
                }
        }

        if (c + 2 < NC) {
            int nstg = stg + 2; if (nstg >= NSTAGE) nstg -= NSTAGE;
            load_chunk(sb + (uint32_t)nstg * STAGE, m0, n0, (c + 2) * KC, tid);
        }
        if (++stg == NSTAGE) stg = 0;
    }

    // epilogue: scale by 1/||t|| and store
    const int qrow = lane >> 2;
    const int qcol = (lane & 3) * 2;
#pragma unroll
    for (int mt = 0; mt < 2; mt++) {
        int r0 = m0 + wm * 32 + mt * 16 + qrow;
        int r1 = r0 + 8;
        float t0 = g_tinv[r0], t1 = g_tinv[r1];
        float* p0 = out + (size_t)r0 * C_CLASSES + n0 + wn * 64 + qcol;
        float* p1 = out + (size_t)r1 * C_CLASSES + n0 + wn * 64 + qcol;
#pragma unroll
        for (int nf = 0; nf < 8; nf++) {
            float2 v0, v1;
            v0.x = acc[mt][nf][0] * t0; v0.y = acc[mt][nf][1] * t0;
            v1.x = acc[mt][nf][2] * t1; v1.y = acc[mt][nf][3] * t1;
            *(float2*)(p0 + nf * 8) = v0;
            *(float2*)(p1 + nf * 8) = v1;
        }
    }
}

// ---------------- launch (side-stream fork/join for prep overlap) ----------------
extern "C" void kernel_launch(void* const* d_in, const int* in_sizes, int n_in,
                              void* d_out, int out_size) {
    const float* ctx    = (const float*)d_in[0];
    const int*   labels = (const int*)d_in[1];
    const float* tgt    = (const float*)d_in[2];
    const int n_ctx = in_sizes[1];
    const int n_tgt = in_sizes[2] / DDIM;

    float* logits    = (float*)d_out;
    float* means_out = (float*)d_out + (size_t)n_tgt * C_CLASSES;

    static cudaStream_t s_side = nullptr;
    static cudaEvent_t  s_fork = nullptr, s_join = nullptr;
    if (!s_side) {
        cudaStreamCreateWithFlags(&s_side, cudaStreamNonBlocking);
        cudaEventCreateWithFlags(&s_fork, cudaEventDisableTiming);
        cudaEventCreateWithFlags(&s_join, cudaEventDisableTiming);
    }
    cudaFuncSetAttribute(gemm_mma_kernel, cudaFuncAttributeMaxDynamicSharedMemorySize, SMEM_BYTES);

    // fork: target fp16 convert runs concurrently with the class-means chain
    cudaEventRecord(s_fork, 0);
    cudaStreamWaitEvent(s_side, s_fork, 0);
    quant_a_kernel<<<(n_tgt + 7) / 8, 256, 0, s_side>>>((const float4*)tgt, n_tgt);
    cudaEventRecord(s_join, s_side);

    zero_kernel<<<1, C_CLASSES>>>();
    count_kernel<<<64, 256>>>(labels, n_ctx);
    scan_kernel<<<1, C_CLASSES>>>();
    scatter_kernel<<<(n_ctx + 255) / 256, 256>>>(labels, n_ctx);
    classsum_kernel<<<dim3(C_CLASSES, DDIM / 256), 256>>>(ctx);
    finalize_kernel<<<C_CLASSES, 256>>>(means_out);

    // join: GEMM needs both branches
    cudaStreamWaitEvent(0, s_join, 0);
    gemm_mma_kernel<<<dim3(C_CLASSES / NT, n_tgt / MT), 256, SMEM_BYTES>>>(logits);
}